// round 7
// baseline (speedup 1.0000x reference)
#include <cuda_runtime.h>
#include <cuda_fp16.h>
#include <cstdint>

// ---------------- Problem constants ----------------
#define N_ROWS     262144
#define K_CODES    1024
#define D_DIM      64
#define M_TILE     128                  // rows per CTA
#define CHUNK      64                   // codes per streamed chunk
#define NUM_CHUNKS (K_CODES / CHUNK)    // 16
#define KCOLS      64                   // fp16 codebook cols (bias now in epilogue)
#define NUM_KS     (KCOLS / 16)         // 4
#define ROWB       144                  // smem row stride bytes: (r*36)%32=4r -> LDSM conflict-free
#define TAU        1.2e-3f              // certification threshold

// ---------------- Static scratch ----------------
__device__ float g_csq[K_CODES];
__device__ float g_Ct[D_DIM * K_CODES];                 // transposed codebook (d-major) for fallback
__device__ __align__(16) __half g_Bg[K_CODES * KCOLS];  // fp16 codebook
__device__ int g_namb;
__device__ int g_amb_rows[N_ROWS];

// ---------------- Helpers ----------------
__device__ __forceinline__ uint32_t smem_u32(const void* p) {
    uint32_t a;
    asm("{ .reg .u64 t; cvta.to.shared.u64 t, %1; cvt.u32.u64 %0, t; }" : "=r"(a) : "l"(p));
    return a;
}
#define LDSM4(r0, r1, r2, r3, a)                                                    \
    asm volatile("ldmatrix.sync.aligned.m8n8.x4.shared.b16 {%0,%1,%2,%3}, [%4];"    \
                 : "=r"(r0), "=r"(r1), "=r"(r2), "=r"(r3) : "r"(a))
#define MMA16816(d, a, b0v, b1v)                                                    \
    asm volatile("mma.sync.aligned.m16n8k16.row.col.f32.f16.f16.f32 "               \
                 "{%0,%1,%2,%3},{%4,%5,%6,%7},{%8,%9},{%0,%1,%2,%3};"               \
                 : "+f"((d)[0]), "+f"((d)[1]), "+f"((d)[2]), "+f"((d)[3])           \
                 : "r"((a)[0]), "r"((a)[1]), "r"((a)[2]), "r"((a)[3]),              \
                   "r"(b0v), "r"(b1v))
#define CP_ASYNC16(dst, src) asm volatile("cp.async.cg.shared.global [%0], [%1], 16;" :: "r"(dst), "l"(src))
#define CP_COMMIT()          asm volatile("cp.async.commit_group;" ::: "memory")
#define CP_WAIT1()           asm volatile("cp.async.wait_group 1;" ::: "memory")
#define CP_WAIT0()           asm volatile("cp.async.wait_group 0;" ::: "memory")

__device__ __forceinline__ uint32_t pack_h2(__half a, __half b) {
    __half2 t(a, b);
    return *reinterpret_cast<uint32_t*>(&t);
}

// ---------------- Exact reference-order arithmetic (bit-validated R3/R5/R6) ----------------
__device__ __forceinline__ float sq_sum_tree64(const float* v) {
    float s[32];
#pragma unroll
    for (int l = 0; l < 32; l++) {
        float a = v[l], b = v[l + 32];
        s[l] = __fadd_rn(__fmul_rn(a, a), __fmul_rn(b, b));
    }
#pragma unroll
    for (int off = 16; off >= 1; off >>= 1)
#pragma unroll
        for (int l = 0; l < 16; l++)
            if (l < off) s[l] = __fadd_rn(s[l], s[l + off]);
    return s[0];
}

__global__ void zero_kernel() { g_namb = 0; }

// ---------------- Prep: exact csq + fp16 codebook + transposed copy ----------------
__global__ void prep_kernel(const float* __restrict__ Cb) {
    int k = blockIdx.x * blockDim.x + threadIdx.x;
    if (k >= K_CODES) return;
    const float* c = Cb + (size_t)k * D_DIM;
    g_csq[k] = sq_sum_tree64(c);
    __half* o = g_Bg + (size_t)k * KCOLS;
#pragma unroll 8
    for (int d = 0; d < D_DIM; d++) {
        float x = c[d];
        o[d] = __float2half_rn(x);
        g_Ct[d * K_CODES + k] = x;      // d-major for coalesced fallback
    }
}

// ---------------- Screen kernel: fp16 HMMA K=64 + epilogue bias + top-2 certify ----------------
#define SM_A   0u                       // 128 x 144B = 18432
#define SM_B   18432u                   // 2 x 64 x 144B = 18432
#define SM_HC  36864u                   // 1024 f32 = 4096 (-0.5*csq)
#define SM_BK  40960u                   // 128 i32
#define SM_TOTAL 41472u

extern "C" __global__ void __launch_bounds__(256, 4)
vq_screen_kernel(const float* __restrict__ X, const float* __restrict__ Cb,
                 float* __restrict__ out_idx, float* __restrict__ out_res,
                 float* __restrict__ out_cb) {
    extern __shared__ __align__(128) char smem[];
    const uint32_t sb = smem_u32(smem);
    const int t = threadIdx.x;
    const int w = t >> 5, l = t & 31;
    const int wr0 = w * 16;                 // warp's row base
    const int m0 = blockIdx.x * M_TILE;
    int* best_sh = (int*)(smem + SM_BK);

    // ---- prologue: stream B chunks 0,1 via cp.async (8 uint4 per code) ----
    {
        const uint4* src = reinterpret_cast<const uint4*>(g_Bg);
#pragma unroll 1
        for (int cc = 0; cc < 2; cc++) {
            const uint4* s2 = src + (size_t)cc * CHUNK * 8;
            uint32_t dstb = sb + SM_B + cc * (CHUNK * ROWB);
            for (int idx = t; idx < CHUNK * 8; idx += 256) {
                int code = idx >> 3, u = idx & 7;
                CP_ASYNC16(dstb + code * ROWB + u * 16, s2 + idx);
            }
            CP_COMMIT();
        }
    }

    // ---- build A (fp16 rows) into smem + bias table (overlaps copies) ----
    {
        const float4* X4 = (const float4*)(X + (size_t)m0 * D_DIM);
#pragma unroll
        for (int i = 0; i < 8; i++) {
            int f = t + i * 256;             // 2048 float4
            int row = f >> 4, d = (f & 15) * 4;
            float4 v = X4[f];
            uint2 hv = make_uint2(pack_h2(__float2half_rn(v.x), __float2half_rn(v.y)),
                                  pack_h2(__float2half_rn(v.z), __float2half_rn(v.w)));
            *reinterpret_cast<uint2*>(smem + SM_A + row * ROWB + d * 2) = hv;
        }
        float* hc = (float*)(smem + SM_HC);
        for (int i = t; i < K_CODES; i += 256) hc[i] = -0.5f * g_csq[i];
    }
    __syncthreads();

    // ---- preload A fragments (4 k-steps x 4 regs) ----
    uint32_t af[NUM_KS][4];
    {
        uint32_t aAddr = sb + SM_A + (uint32_t)(wr0 + (l & 15)) * ROWB + (uint32_t)(l >> 4) * 16;
#pragma unroll
        for (int ks = 0; ks < NUM_KS; ks++)
            LDSM4(af[ks][0], af[ks][1], af[ks][2], af[ks][3], aAddr + ks * 32);
    }

    const uint32_t bLane = (uint32_t)(l & 7) * ROWB + ((uint32_t)(l >> 3) & 1) * 16 +
                           ((uint32_t)(l >> 4) & 1) * (8 * ROWB);

    // top-2 state: row q = wr0 + (l>>2) and row q+8
    float bmA1 = -3.0e38f, bmA2 = -3.0e38f, bmB1 = -3.0e38f, bmB2 = -3.0e38f;
    int bkA = 0, bkB = 0;

    for (int c = 0; c < NUM_CHUNKS; c++) {
        if (c >= NUM_CHUNKS - 2) { CP_WAIT0(); } else { CP_WAIT1(); }
        __syncthreads();

        const uint32_t bufB = sb + SM_B + (uint32_t)(c & 1) * (CHUNK * ROWB);
        float acc[8][4];
#pragma unroll
        for (int nt = 0; nt < 8; nt++)
#pragma unroll
            for (int j = 0; j < 4; j++) acc[nt][j] = 0.f;

#pragma unroll
        for (int np = 0; np < 4; np++) {           // 16 codes per pair-group
            const uint32_t bBase = bufB + (uint32_t)np * (16 * ROWB) + bLane;
#pragma unroll
            for (int ks = 0; ks < NUM_KS; ks++) {
                uint32_t b0, b1, b2, b3;
                LDSM4(b0, b1, b2, b3, bBase + ks * 32);
                MMA16816(acc[np * 2],     af[ks], b0, b1);
                MMA16816(acc[np * 2 + 1], af[ks], b2, b3);
            }
        }
        __syncthreads();   // done reading buf (before refill)

        // refill this buffer with chunk c+2
        if (c + 2 < NUM_CHUNKS) {
            const uint4* s2 = reinterpret_cast<const uint4*>(g_Bg) + (size_t)(c + 2) * CHUNK * 8;
            uint32_t dstb = sb + SM_B + (uint32_t)(c & 1) * (CHUNK * ROWB);
            for (int idx = t; idx < CHUNK * 8; idx += 256) {
                int code = idx >> 3, u = idx & 7;
                CP_ASYNC16(dstb + code * ROWB + u * 16, s2 + idx);
            }
            CP_COMMIT();
        }

        // ---- epilogue: bias + running top-2 (k ascending; strict > keeps lowest k) ----
        const float* hc = (const float*)(smem + SM_HC);
#pragma unroll
        for (int nt = 0; nt < 8; nt++) {
            int k0 = c * CHUNK + nt * 8 + (l & 3) * 2;
            float2 hcv = *reinterpret_cast<const float2*>(hc + k0);
            float v0 = acc[nt][0] + hcv.x, v1 = acc[nt][1] + hcv.y;
            float v2 = acc[nt][2] + hcv.x, v3 = acc[nt][3] + hcv.y;
            if (v0 > bmA1) { bmA2 = bmA1; bmA1 = v0; bkA = k0; }     else bmA2 = fmaxf(bmA2, v0);
            if (v1 > bmA1) { bmA2 = bmA1; bmA1 = v1; bkA = k0 + 1; } else bmA2 = fmaxf(bmA2, v1);
            if (v2 > bmB1) { bmB2 = bmB1; bmB1 = v2; bkB = k0; }     else bmB2 = fmaxf(bmB2, v2);
            if (v3 > bmB1) { bmB2 = bmB1; bmB1 = v3; bkB = k0 + 1; } else bmB2 = fmaxf(bmB2, v3);
        }
    }

    // ---- merge across the 4 lanes of each quad (same rows, disjoint cols) ----
#pragma unroll
    for (int off = 1; off <= 2; off <<= 1) {
        float o1, o2; int ok;
        o1 = __shfl_xor_sync(0xffffffffu, bmA1, off);
        o2 = __shfl_xor_sync(0xffffffffu, bmA2, off);
        ok = __shfl_xor_sync(0xffffffffu, bkA, off);
        {
            bool bw = (o1 > bmA1) || (o1 == bmA1 && ok < bkA);
            float n2 = fmaxf(fminf(bmA1, o1), fmaxf(bmA2, o2));
            if (bw) { bmA1 = o1; bkA = ok; }
            bmA2 = n2;
        }
        o1 = __shfl_xor_sync(0xffffffffu, bmB1, off);
        o2 = __shfl_xor_sync(0xffffffffu, bmB2, off);
        ok = __shfl_xor_sync(0xffffffffu, bkB, off);
        {
            bool bw = (o1 > bmB1) || (o1 == bmB1 && ok < bkB);
            float n2 = fmaxf(fminf(bmB1, o1), fmaxf(bmB2, o2));
            if (bw) { bmB1 = o1; bkB = ok; }
            bmB2 = n2;
        }
    }
    if ((l & 3) == 0) {
        int rowA = wr0 + (l >> 2);
        int rowB = rowA + 8;
        best_sh[rowA] = bkA;
        best_sh[rowB] = bkB;
        out_idx[m0 + rowA] = (float)bkA;
        out_idx[m0 + rowB] = (float)bkB;
        if (bmA1 - bmA2 <= TAU) { int a = atomicAdd(&g_namb, 1); g_amb_rows[a] = m0 + rowA; }
        if (bmB1 - bmB2 <= TAU) { int a = atomicAdd(&g_namb, 1); g_amb_rows[a] = m0 + rowB; }
    }
    __syncthreads();

    // ---- outputs: gather + residual ----
#pragma unroll
    for (int i = 0; i < (M_TILE * D_DIM) / 256; i++) {   // 32 iters
        int f = t + i * 256;
        int row = f >> 6, d = f & 63;
        int bk = best_sh[row];
        size_t g = (size_t)(m0 + row) * D_DIM + d;
        float cv = __ldg(&Cb[(size_t)bk * D_DIM + d]);
        float xv = __ldg(&X[g]);
        out_cb[g]  = cv;
        out_res[g] = __fsub_rn(xv, cv);
    }
}

// ---------------- Exact fallback: warp-per-row, no block barriers ----------------
__global__ void __launch_bounds__(128)
vq_fallback_kernel(const float* __restrict__ X, const float* __restrict__ Cb,
                   float* __restrict__ out_idx, float* __restrict__ out_res,
                   float* __restrict__ out_cb) {
    __shared__ float sx[4][D_DIM];
    const int t = threadIdx.x;
    const int w = t >> 5, l = t & 31;
    const int n = g_namb;
    for (int j = blockIdx.x * 4 + w; j < n; j += gridDim.x * 4) {
        const int row = g_amb_rows[j];
        const float xlo = X[(size_t)row * D_DIM + l];
        const float xhi = X[(size_t)row * D_DIM + 32 + l];
        // exact tree xsq via shfl_down (lane-0 dataflow == sq_sum_tree64)
        float s = __fadd_rn(__fmul_rn(xlo, xlo), __fmul_rn(xhi, xhi));
#pragma unroll
        for (int off = 16; off >= 1; off >>= 1) {
            float o = __shfl_down_sync(0xffffffffu, s, off);
            s = __fadd_rn(s, o);
        }
        const float xsq = __shfl_sync(0xffffffffu, s, 0);
        sx[w][l] = xlo;
        sx[w][l + 32] = xhi;
        __syncwarp();

        float bs = 3.0e38f;
        int bk = 0;
#pragma unroll 1
        for (int c = 0; c < K_CODES / 32; c++) {
            int k = c * 32 + l;
            float acc = 0.f;
#pragma unroll
            for (int d = 0; d < D_DIM; d++)
                acc = fmaf(sx[w][d], __ldg(&g_Ct[d * K_CODES + k]), acc);
            float sc = __fadd_rn(__fsub_rn(xsq, 2.0f * acc), g_csq[k]);
            if (sc < bs) { bs = sc; bk = k; }   // k ascending: strict < keeps lowest
        }
#pragma unroll
        for (int off = 16; off; off >>= 1) {
            float os = __shfl_xor_sync(0xffffffffu, bs, off);
            int ok = __shfl_xor_sync(0xffffffffu, bk, off);
            if (os < bs || (os == bs && ok < bk)) { bs = os; bk = ok; }
        }
        const int k1 = __shfl_sync(0xffffffffu, bk, 0);
        if (l == 0) out_idx[row] = (float)k1;
        // outputs: lane l covers d=l and d=l+32
        {
            size_t g = (size_t)row * D_DIM + l;
            float cv0 = __ldg(&Cb[(size_t)k1 * D_DIM + l]);
            float cv1 = __ldg(&Cb[(size_t)k1 * D_DIM + 32 + l]);
            out_cb[g]       = cv0;
            out_cb[g + 32]  = cv1;
            out_res[g]      = __fsub_rn(xlo, cv0);
            out_res[g + 32] = __fsub_rn(xhi, cv1);
        }
        __syncwarp();
    }
}

// ---------------- Launch ----------------
extern "C" void kernel_launch(void* const* d_in, const int* in_sizes, int n_in,
                              void* d_out, int out_size) {
    const float* X = (const float*)d_in[0];
    const float* C = (const float*)d_in[1];
    float* out_idx = (float*)d_out;
    float* out_res = out_idx + N_ROWS;
    float* out_cb  = out_res + (size_t)N_ROWS * D_DIM;

    cudaFuncSetAttribute(vq_screen_kernel,
                         cudaFuncAttributeMaxDynamicSharedMemorySize, SM_TOTAL);

    zero_kernel<<<1, 1>>>();
    prep_kernel<<<(K_CODES + 255) / 256, 256>>>(C);
    vq_screen_kernel<<<N_ROWS / M_TILE, 256, SM_TOTAL>>>(X, C, out_idx, out_res, out_cb);
    vq_fallback_kernel<<<2048, 128>>>(X, C, out_idx, out_res, out_cb);
}

// round 8
// speedup vs baseline: 1.2420x; 1.2420x over previous
#include <cuda_runtime.h>
#include <cuda_fp16.h>
#include <cstdint>

// ---------------- Problem constants ----------------
#define N_ROWS     262144
#define K_CODES    1024
#define D_DIM      64
#define M_TILE     128                  // rows per CTA
#define CHUNK      64                   // codes per chunk
#define NUM_CHUNKS (K_CODES / CHUNK)    // 16
#define KCOLS      64                   // fp16 codebook cols
#define NUM_KS     (KCOLS / 16)         // 4
#define ROWB       144                  // A smem row stride bytes (LDSM conflict-free)
#define TAU        1.2e-3f              // certification threshold

// ---------------- Static scratch ----------------
__device__ float g_csq[K_CODES];
__device__ float g_Ct[D_DIM * K_CODES];                 // transposed codebook (d-major) for fallback
// B in HMMA fragment order: [gtile(128)][half(2)][lane(32)] x uint4
__device__ __align__(16) uint32_t g_Bfrag[(K_CODES / 8) * 2 * 32 * 4];
__device__ int g_namb;
__device__ int g_amb_rows[N_ROWS];

// ---------------- Helpers ----------------
__device__ __forceinline__ uint32_t smem_u32(const void* p) {
    uint32_t a;
    asm("{ .reg .u64 t; cvta.to.shared.u64 t, %1; cvt.u32.u64 %0, t; }" : "=r"(a) : "l"(p));
    return a;
}
#define LDSM4(r0, r1, r2, r3, a)                                                    \
    asm volatile("ldmatrix.sync.aligned.m8n8.x4.shared.b16 {%0,%1,%2,%3}, [%4];"    \
                 : "=r"(r0), "=r"(r1), "=r"(r2), "=r"(r3) : "r"(a))
#define MMA16816(d, a, b0v, b1v)                                                    \
    asm volatile("mma.sync.aligned.m16n8k16.row.col.f32.f16.f16.f32 "               \
                 "{%0,%1,%2,%3},{%4,%5,%6,%7},{%8,%9},{%0,%1,%2,%3};"               \
                 : "+f"((d)[0]), "+f"((d)[1]), "+f"((d)[2]), "+f"((d)[3])           \
                 : "r"((a)[0]), "r"((a)[1]), "r"((a)[2]), "r"((a)[3]),              \
                   "r"(b0v), "r"(b1v))

__device__ __forceinline__ uint32_t pack_h2(float a, float b) {
    __half2 t(__float2half_rn(a), __float2half_rn(b));
    return *reinterpret_cast<uint32_t*>(&t);
}

// ---------------- Exact reference-order arithmetic (bit-validated R3/R5/R6) ----------------
__device__ __forceinline__ float sq_sum_tree64(const float* v) {
    float s[32];
#pragma unroll
    for (int l = 0; l < 32; l++) {
        float a = v[l], b = v[l + 32];
        s[l] = __fadd_rn(__fmul_rn(a, a), __fmul_rn(b, b));
    }
#pragma unroll
    for (int off = 16; off >= 1; off >>= 1)
#pragma unroll
        for (int l = 0; l < 16; l++)
            if (l < off) s[l] = __fadd_rn(s[l], s[l + off]);
    return s[0];
}

// ---------------- Prep: exact csq + transposed copy (+ zero amb counter) ----------------
__global__ void prep_kernel(const float* __restrict__ Cb) {
    int k = blockIdx.x * blockDim.x + threadIdx.x;
    if (k == 0) g_namb = 0;
    if (k >= K_CODES) return;
    const float* c = Cb + (size_t)k * D_DIM;
    g_csq[k] = sq_sum_tree64(c);
#pragma unroll 8
    for (int d = 0; d < D_DIM; d++)
        g_Ct[d * K_CODES + k] = c[d];   // d-major for coalesced fallback
}

// ---------------- Prep: fp16 codebook in m16n8k16 B-fragment order ----------------
// b0 = {B[2g][n], B[2g+1][n]}, b1 = {B[2g+8][n], B[2g+9][n]}, n = lane>>2, g = lane&3,
// where B[k][n] = Cb[gt*8 + n][ks*16 + k].
__global__ void prep_frag_kernel(const float* __restrict__ Cb) {
    int tid = blockIdx.x * blockDim.x + threadIdx.x;   // 0..4095
    int gt = tid >> 5, l = tid & 31;
    int code = gt * 8 + (l >> 2);
    int kb = 2 * (l & 3);
    const float* cr = Cb + (size_t)code * D_DIM;
    uint32_t f[8];
#pragma unroll
    for (int ks = 0; ks < 4; ks++) {
        float2 v0 = *reinterpret_cast<const float2*>(cr + ks * 16 + kb);
        float2 v1 = *reinterpret_cast<const float2*>(cr + ks * 16 + kb + 8);
        f[ks * 2 + 0] = pack_h2(v0.x, v0.y);
        f[ks * 2 + 1] = pack_h2(v1.x, v1.y);
    }
    uint4* dst = reinterpret_cast<uint4*>(g_Bfrag);
    dst[(gt * 2 + 0) * 32 + l] = make_uint4(f[0], f[1], f[2], f[3]);
    dst[(gt * 2 + 1) * 32 + l] = make_uint4(f[4], f[5], f[6], f[7]);
}

// ---------------- Screen kernel: barrier-free HMMA + epilogue bias + top-2 certify ----------------
#define SM_A   0u                       // 128 x 144B = 18432
#define SM_HC  18432u                   // 1024 f32 = 4096 (-0.5*csq)
#define SM_BK  22528u                   // 128 i32
#define SM_TOTAL 23040u

extern "C" __global__ void __launch_bounds__(256, 2)
vq_screen_kernel(const float* __restrict__ X, const float* __restrict__ Cb,
                 float* __restrict__ out_idx, float* __restrict__ out_res,
                 float* __restrict__ out_cb) {
    extern __shared__ __align__(128) char smem[];
    const uint32_t sb = smem_u32(smem);
    const int t = threadIdx.x;
    const int w = t >> 5, l = t & 31;
    const int wr0 = w * 16;                 // warp's row base
    const int m0 = blockIdx.x * M_TILE;
    int* best_sh = (int*)(smem + SM_BK);

    // ---- build A (fp16 rows) into smem + bias table ----
    {
        const float4* X4 = (const float4*)(X + (size_t)m0 * D_DIM);
#pragma unroll
        for (int i = 0; i < 8; i++) {
            int f = t + i * 256;             // 2048 float4
            int row = f >> 4, d = (f & 15) * 4;
            float4 v = X4[f];
            uint2 hv = make_uint2(pack_h2(v.x, v.y), pack_h2(v.z, v.w));
            *reinterpret_cast<uint2*>(smem + SM_A + row * ROWB + d * 2) = hv;
        }
        float* hc = (float*)(smem + SM_HC);
        for (int i = t; i < K_CODES; i += 256) hc[i] = -0.5f * g_csq[i];
    }
    __syncthreads();

    // ---- preload A fragments (4 k-steps x 4 regs) ----
    uint32_t af[NUM_KS][4];
    {
        uint32_t aAddr = sb + SM_A + (uint32_t)(wr0 + (l & 15)) * ROWB + (uint32_t)(l >> 4) * 16;
#pragma unroll
        for (int ks = 0; ks < NUM_KS; ks++)
            LDSM4(af[ks][0], af[ks][1], af[ks][2], af[ks][3], aAddr + ks * 32);
    }

    // top-2 state: row q = wr0 + (l>>2) and row q+8
    float bmA1 = -3.0e38f, bmA2 = -3.0e38f, bmB1 = -3.0e38f, bmB2 = -3.0e38f;
    int bkA = 0, bkB = 0;

    const float* hc = (const float*)(smem + SM_HC);

    for (int c = 0; c < NUM_CHUNKS; c++) {
        float acc[8][4];
#pragma unroll
        for (int nt = 0; nt < 8; nt++)
#pragma unroll
            for (int j = 0; j < 4; j++) acc[nt][j] = 0.f;

        const uint4* bf = reinterpret_cast<const uint4*>(g_Bfrag) + (size_t)c * 8 * 2 * 32 + l;
#pragma unroll
        for (int nt = 0; nt < 8; nt++) {
            uint4 f0 = __ldg(bf + (nt * 2 + 0) * 32);
            uint4 f1 = __ldg(bf + (nt * 2 + 1) * 32);
            MMA16816(acc[nt], af[0], f0.x, f0.y);
            MMA16816(acc[nt], af[1], f0.z, f0.w);
            MMA16816(acc[nt], af[2], f1.x, f1.y);
            MMA16816(acc[nt], af[3], f1.z, f1.w);
        }

        // ---- epilogue: bias + running top-2 (k ascending; strict > keeps lowest k) ----
#pragma unroll
        for (int nt = 0; nt < 8; nt++) {
            int k0 = c * CHUNK + nt * 8 + (l & 3) * 2;
            float2 hcv = *reinterpret_cast<const float2*>(hc + k0);
            float v0 = acc[nt][0] + hcv.x, v1 = acc[nt][1] + hcv.y;
            float v2 = acc[nt][2] + hcv.x, v3 = acc[nt][3] + hcv.y;
            if (v0 > bmA1) { bmA2 = bmA1; bmA1 = v0; bkA = k0; }     else bmA2 = fmaxf(bmA2, v0);
            if (v1 > bmA1) { bmA2 = bmA1; bmA1 = v1; bkA = k0 + 1; } else bmA2 = fmaxf(bmA2, v1);
            if (v2 > bmB1) { bmB2 = bmB1; bmB1 = v2; bkB = k0; }     else bmB2 = fmaxf(bmB2, v2);
            if (v3 > bmB1) { bmB2 = bmB1; bmB1 = v3; bkB = k0 + 1; } else bmB2 = fmaxf(bmB2, v3);
        }
    }

    // ---- merge across the 4 lanes of each quad (same rows, disjoint cols) ----
#pragma unroll
    for (int off = 1; off <= 2; off <<= 1) {
        float o1, o2; int ok;
        o1 = __shfl_xor_sync(0xffffffffu, bmA1, off);
        o2 = __shfl_xor_sync(0xffffffffu, bmA2, off);
        ok = __shfl_xor_sync(0xffffffffu, bkA, off);
        {
            bool bw = (o1 > bmA1) || (o1 == bmA1 && ok < bkA);
            float n2 = fmaxf(fminf(bmA1, o1), fmaxf(bmA2, o2));
            if (bw) { bmA1 = o1; bkA = ok; }
            bmA2 = n2;
        }
        o1 = __shfl_xor_sync(0xffffffffu, bmB1, off);
        o2 = __shfl_xor_sync(0xffffffffu, bmB2, off);
        ok = __shfl_xor_sync(0xffffffffu, bkB, off);
        {
            bool bw = (o1 > bmB1) || (o1 == bmB1 && ok < bkB);
            float n2 = fmaxf(fminf(bmB1, o1), fmaxf(bmB2, o2));
            if (bw) { bmB1 = o1; bkB = ok; }
            bmB2 = n2;
        }
    }
    if ((l & 3) == 0) {
        int rowA = wr0 + (l >> 2);
        int rowB = rowA + 8;
        best_sh[rowA] = bkA;
        best_sh[rowB] = bkB;
        out_idx[m0 + rowA] = (float)bkA;
        out_idx[m0 + rowB] = (float)bkB;
        if (bmA1 - bmA2 <= TAU) { int a = atomicAdd(&g_namb, 1); g_amb_rows[a] = m0 + rowA; }
        if (bmB1 - bmB2 <= TAU) { int a = atomicAdd(&g_namb, 1); g_amb_rows[a] = m0 + rowB; }
    }
    __syncthreads();

    // ---- outputs: gather + residual ----
#pragma unroll
    for (int i = 0; i < (M_TILE * D_DIM) / 256; i++) {   // 32 iters
        int f = t + i * 256;
        int row = f >> 6, d = f & 63;
        int bk = best_sh[row];
        size_t g = (size_t)(m0 + row) * D_DIM + d;
        float cv = __ldg(&Cb[(size_t)bk * D_DIM + d]);
        float xv = __ldg(&X[g]);
        out_cb[g]  = cv;
        out_res[g] = __fsub_rn(xv, cv);
    }
}

// ---------------- Exact fallback (R6-measured 78us version: block-per-row, coalesced) ----------------
__global__ void __launch_bounds__(128)
vq_fallback_kernel(const float* __restrict__ X, const float* __restrict__ Cb,
                   float* __restrict__ out_idx, float* __restrict__ out_res,
                   float* __restrict__ out_cb) {
    __shared__ float xrow[D_DIM];
    __shared__ float xsq_s;
    __shared__ float rs[4];
    __shared__ int rk[4];
    const int t = threadIdx.x;
    const int n = g_namb;
    for (int j = blockIdx.x; j < n; j += gridDim.x) {
        const int row = g_amb_rows[j];
        __syncthreads();
        if (t < D_DIM) xrow[t] = X[(size_t)row * D_DIM + t];
        __syncthreads();
        if (t == 0) xsq_s = sq_sum_tree64(xrow);
        __syncthreads();
        const float xsq = xsq_s;
        float bs = 3.0e38f;
        int bk = 0;
#pragma unroll
        for (int c = 0; c < K_CODES / 128; c++) {
            int k = c * 128 + t;
            float acc = 0.f;
            // identical value sequence to R3 (d ascending), coalesced via g_Ct
#pragma unroll 8
            for (int d = 0; d < D_DIM; d++)
                acc = fmaf(xrow[d], __ldg(&g_Ct[d * K_CODES + k]), acc);
            float s = __fadd_rn(__fsub_rn(xsq, 2.0f * acc), g_csq[k]);
            if (s < bs) { bs = s; bk = k; }   // k ascending: strict < keeps lowest
        }
#pragma unroll
        for (int off = 16; off; off >>= 1) {
            float os = __shfl_xor_sync(0xffffffffu, bs, off);
            int ok = __shfl_xor_sync(0xffffffffu, bk, off);
            if (os < bs || (os == bs && ok < bk)) { bs = os; bk = ok; }
        }
        if ((t & 31) == 0) { rs[t >> 5] = bs; rk[t >> 5] = bk; }
        __syncthreads();
        if (t == 0) {
            for (int wi = 1; wi < 4; wi++)
                if (rs[wi] < rs[0] || (rs[wi] == rs[0] && rk[wi] < rk[0])) {
                    rs[0] = rs[wi]; rk[0] = rk[wi];
                }
            out_idx[row] = (float)rk[0];
        }
        __syncthreads();
        const int k1 = rk[0];
        if (t < D_DIM) {
            size_t g = (size_t)row * D_DIM + t;
            float cv = __ldg(&Cb[(size_t)k1 * D_DIM + t]);
            out_cb[g]  = cv;
            out_res[g] = __fsub_rn(xrow[t], cv);
        }
    }
}

// ---------------- Launch ----------------
extern "C" void kernel_launch(void* const* d_in, const int* in_sizes, int n_in,
                              void* d_out, int out_size) {
    const float* X = (const float*)d_in[0];
    const float* C = (const float*)d_in[1];
    float* out_idx = (float*)d_out;
    float* out_res = out_idx + N_ROWS;
    float* out_cb  = out_res + (size_t)N_ROWS * D_DIM;

    cudaFuncSetAttribute(vq_screen_kernel,
                         cudaFuncAttributeMaxDynamicSharedMemorySize, SM_TOTAL);

    prep_kernel<<<(K_CODES + 255) / 256, 256>>>(C);
    prep_frag_kernel<<<16, 256>>>(C);
    vq_screen_kernel<<<N_ROWS / M_TILE, 256, SM_TOTAL>>>(X, C, out_idx, out_res, out_cb);
    vq_fallback_kernel<<<2048, 128>>>(X, C, out_idx, out_res, out_cb);
}